// round 2
// baseline (speedup 1.0000x reference)
#include <cuda_runtime.h>
#include <cuda_bf16.h>

#define N_NODES 100000
#define N_EDGES 1000000
#define HID 64

// Scratch (device globals: allocation-free per harness rules)
__device__ __align__(16) float g_buf[N_NODES * HID];   // dinv-scaled transformed features (gather source)
__device__ __align__(16) float s_buf[N_NODES * HID];   // aggregation accumulator (init = self loop term)
__device__ __align__(16) float h_buf[N_NODES * HID];   // finalized layer input
__device__ float dinv_buf[N_NODES];
__device__ int   deg_buf[N_NODES];

// ---------------- degree / norm ----------------
__global__ void k_init_deg() {
    int i = blockIdx.x * blockDim.x + threadIdx.x;
    if (i < N_NODES) deg_buf[i] = 1;            // self loop
}

__global__ void k_count_deg(const int* __restrict__ ei) {
    int e = blockIdx.x * blockDim.x + threadIdx.x;
    if (e < N_EDGES) {
        int c = ei[N_EDGES + e];                // col = target
        if (c >= 0 && c < N_NODES) atomicAdd(&deg_buf[c], 1);
    }
}

__global__ void k_dinv() {
    int i = blockIdx.x * blockDim.x + threadIdx.x;
    if (i < N_NODES) dinv_buf[i] = rsqrtf((float)deg_buf[i]);
}

// ---------------- layer 1 transform (2 -> 64), writes g and s ----------------
__global__ void k_transform1(const float* __restrict__ x, const float* __restrict__ W1) {
    int idx = blockIdx.x * blockDim.x + threadIdx.x;
    if (idx < N_NODES * HID) {
        int node = idx >> 6;
        int f = idx & 63;
        float v = x[node * 2] * W1[f] + x[node * 2 + 1] * W1[HID + f];
        v *= dinv_buf[node];
        g_buf[idx] = v;
        s_buf[idx] = v;
    }
}

// ---------------- edge scatter: s[col] += g[row], vectorized red.v4 ----------------
__global__ void k_scatter(const int* __restrict__ ei) {
    int idx = blockIdx.x * blockDim.x + threadIdx.x;   // N_EDGES*16 threads
    if (idx < N_EDGES * 16) {
        int e = idx >> 4;
        int c = idx & 15;
        int r   = ei[e];
        int col = ei[N_EDGES + e];
        const float4 v = *reinterpret_cast<const float4*>(g_buf + r * HID + c * 4);
        float* dst = s_buf + col * HID + c * 4;
        asm volatile("red.global.add.v4.f32 [%0], {%1,%2,%3,%4};"
                     :: "l"(dst), "f"(v.x), "f"(v.y), "f"(v.z), "f"(v.w)
                     : "memory");
    }
}

// ---------------- finalize: h = (relu?)(dinv*s + b) ----------------
__global__ void k_finalize(const float* __restrict__ bias, int do_relu) {
    int idx = blockIdx.x * blockDim.x + threadIdx.x;
    if (idx < N_NODES * HID) {
        int node = idx >> 6;
        int f = idx & 63;
        float v = dinv_buf[node] * s_buf[idx] + bias[f];
        if (do_relu) v = fmaxf(v, 0.f);
        h_buf[idx] = v;
    }
}

// ---------------- 64x64 GEMM over node tiles (in = h_buf) ----------------
// scale_dinv -> conv transform: g = dinv * (h@W), dual-write g & s
// bias+relu  -> dense layer 4:  g = relu(h@W + b)
__global__ void k_gemm64(const float* __restrict__ W, const float* __restrict__ bias,
                         int dual_write, int scale_dinv, int do_relu) {
    __shared__ float Ws[HID][HID + 1];
    __shared__ float Xs[HID][HID + 1];
    int tx = threadIdx.x;                 // 256 threads
    int base = blockIdx.x * HID;          // 64 nodes per block

    for (int l = tx; l < HID * HID; l += 256)
        Ws[l >> 6][l & 63] = W[l];
    for (int l = tx; l < HID * HID; l += 256) {
        int node = base + (l >> 6);
        Xs[l >> 6][l & 63] = (node < N_NODES) ? h_buf[node * HID + (l & 63)] : 0.f;
    }
    __syncthreads();

    int r = tx >> 2;      // node within tile
    int q = tx & 3;       // feature phase
    float acc[16];
#pragma unroll
    for (int j = 0; j < 16; j++) acc[j] = 0.f;

#pragma unroll 8
    for (int k = 0; k < HID; k++) {
        float a = Xs[r][k];
#pragma unroll
        for (int j = 0; j < 16; j++)
            acc[j] += a * Ws[k][q + 4 * j];
    }

    int node = base + r;
    if (node < N_NODES) {
        float sc = scale_dinv ? dinv_buf[node] : 1.f;
#pragma unroll
        for (int j = 0; j < 16; j++) {
            int f = q + 4 * j;
            float v = acc[j];
            if (bias) v += bias[f];
            v *= sc;
            if (do_relu) v = fmaxf(v, 0.f);
            g_buf[node * HID + f] = v;
            if (dual_write) s_buf[node * HID + f] = v;
        }
    }
}

// ---------------- final projection: out[i] = g[i,:] . W5 + b5 ----------------
__global__ void k_final(const float* __restrict__ W5, const float* __restrict__ b5,
                        float* __restrict__ out) {
    int gw = (blockIdx.x * blockDim.x + threadIdx.x) >> 5;
    int lane = threadIdx.x & 31;
    if (gw < N_NODES) {
        const float* row = g_buf + gw * HID;
        float v = row[lane] * W5[lane] + row[lane + 32] * W5[lane + 32];
#pragma unroll
        for (int o = 16; o > 0; o >>= 1)
            v += __shfl_down_sync(0xffffffffu, v, o);
        if (lane == 0) out[gw] = v + b5[0];
    }
}

static inline void launch_conv_transform(const float* W) {
    k_gemm64<<<(N_NODES + HID - 1) / HID, 256>>>(W, nullptr, /*dual*/1, /*scale*/1, /*relu*/0);
}

extern "C" void kernel_launch(void* const* d_in, const int* in_sizes, int n_in,
                              void* d_out, int out_size) {
    const float* x  = (const float*)d_in[0];
    const int*   ei = (const int*)d_in[1];     // edge_index is int32 (JAX x64 disabled)
    // d_in[2] = batch (unused)
    const float* W1 = (const float*)d_in[3];
    const float* b1 = (const float*)d_in[4];
    const float* W2 = (const float*)d_in[5];
    const float* b2 = (const float*)d_in[6];
    const float* W3 = (const float*)d_in[7];
    const float* b3 = (const float*)d_in[8];
    const float* W4 = (const float*)d_in[9];
    const float* b4 = (const float*)d_in[10];
    const float* W5 = (const float*)d_in[11];
    const float* b5 = (const float*)d_in[12];
    float* out = (float*)d_out;

    const int nbN  = (N_NODES + 255) / 256;
    const int nbE  = (N_EDGES + 255) / 256;
    const int nbF  = (N_NODES * HID + 255) / 256;
    const int nbSc = (N_EDGES * 16 + 255) / 256;
    const int nbG  = (N_NODES + HID - 1) / HID;
    const int nbW  = (N_NODES * 32 + 255) / 256;

    // degrees + symmetric norm
    k_init_deg<<<nbN, 256>>>();
    k_count_deg<<<nbE, 256>>>(ei);
    k_dinv<<<nbN, 256>>>();

    // conv1: transform(2->64) -> scatter -> finalize(relu)
    k_transform1<<<nbF, 256>>>(x, W1);
    k_scatter<<<nbSc, 256>>>(ei);
    k_finalize<<<nbF, 256>>>(b1, 1);

    // conv2
    launch_conv_transform(W2);
    k_scatter<<<nbSc, 256>>>(ei);
    k_finalize<<<nbF, 256>>>(b2, 1);

    // conv3 (no relu)
    launch_conv_transform(W3);
    k_scatter<<<nbSc, 256>>>(ei);
    k_finalize<<<nbF, 256>>>(b3, 0);

    // dense layer 4: g = relu(h@W4 + b4)
    k_gemm64<<<nbG, 256>>>(W4, b4, /*dual*/0, /*scale*/0, /*relu*/1);

    // output projection
    k_final<<<nbW, 256>>>(W5, b5, out);
}

// round 3
// speedup vs baseline: 1.4727x; 1.4727x over previous
#include <cuda_runtime.h>
#include <cuda_bf16.h>

#define N_NODES 100000
#define N_EDGES 1000000
#define HID 64
#define SCAN_BS 512
#define NB_SCAN ((N_NODES + SCAN_BS - 1) / SCAN_BS)   // 196

// Scratch (device globals: allocation-free per harness rules)
__device__ __align__(16) float g_buf[N_NODES * HID];   // dinv-scaled transformed features
__device__ __align__(16) float h_buf[N_NODES * HID];   // aggregated+finalized layer output
__device__ float dinv_buf[N_NODES];
__device__ int   deg_buf[N_NODES];
__device__ int   incl_buf[N_NODES];        // block-local inclusive scan of deg
__device__ int   blksum_buf[NB_SCAN];
__device__ int   blkoff_buf[NB_SCAN];
__device__ int   csr_off[N_NODES + 1];
__device__ int   cursor_buf[N_NODES];
__device__ int   csr_row[N_EDGES];         // source nodes grouped by target

// ---------------- degree ----------------
__global__ void k_zero_deg() {
    int i = blockIdx.x * blockDim.x + threadIdx.x;
    if (i < N_NODES) deg_buf[i] = 0;
}

__global__ void k_count_deg(const int* __restrict__ ei) {
    int e = blockIdx.x * blockDim.x + threadIdx.x;
    if (e < N_EDGES) atomicAdd(&deg_buf[ei[N_EDGES + e]], 1);
}

// ---------------- 3-phase exclusive scan of deg -> csr_off ----------------
__global__ void k_scan1() {
    __shared__ int sh[SCAN_BS];
    int t = threadIdx.x;
    int i = blockIdx.x * SCAN_BS + t;
    int v = (i < N_NODES) ? deg_buf[i] : 0;
    sh[t] = v;
    __syncthreads();
    for (int off = 1; off < SCAN_BS; off <<= 1) {
        int u = (t >= off) ? sh[t - off] : 0;
        __syncthreads();
        sh[t] += u;
        __syncthreads();
    }
    if (i < N_NODES) incl_buf[i] = sh[t];
    if (t == SCAN_BS - 1) blksum_buf[blockIdx.x] = sh[t];
}

__global__ void k_scan2() {   // single block, 256 threads >= NB_SCAN
    __shared__ int sh[256];
    int t = threadIdx.x;
    int v = (t < NB_SCAN) ? blksum_buf[t] : 0;
    sh[t] = v;
    __syncthreads();
    for (int off = 1; off < 256; off <<= 1) {
        int u = (t >= off) ? sh[t - off] : 0;
        __syncthreads();
        sh[t] += u;
        __syncthreads();
    }
    if (t < NB_SCAN) blkoff_buf[t] = sh[t] - v;   // exclusive
}

__global__ void k_scan3() {
    int i = blockIdx.x * blockDim.x + threadIdx.x;
    if (i < N_NODES) {
        int d = deg_buf[i];
        int excl = incl_buf[i] - d + blkoff_buf[i / SCAN_BS];
        csr_off[i] = excl;
        cursor_buf[i] = excl;
        dinv_buf[i] = rsqrtf((float)(d + 1));     // +1 self loop
        if (i == 0) csr_off[N_NODES] = N_EDGES;
    }
}

__global__ void k_fill(const int* __restrict__ ei) {
    int e = blockIdx.x * blockDim.x + threadIdx.x;
    if (e < N_EDGES) {
        int r = ei[e];
        int c = ei[N_EDGES + e];
        int pos = atomicAdd(&cursor_buf[c], 1);
        csr_row[pos] = r;
    }
}

// ---------------- layer 1 transform (2 -> 64): g = dinv * (x @ W1) ----------------
__global__ void k_transform1(const float* __restrict__ x, const float* __restrict__ W1) {
    int idx = blockIdx.x * blockDim.x + threadIdx.x;
    if (idx < N_NODES * HID) {
        int node = idx >> 6;
        int f = idx & 63;
        float v = x[node * 2] * W1[f] + x[node * 2 + 1] * W1[HID + f];
        g_buf[idx] = v * dinv_buf[node];
    }
}

// ---------------- fused gather-aggregate + finalize ----------------
// h[i] = relu?( dinv[i] * (g[i] + sum_{j in N(i)} g[j]) + b )
__global__ void k_gather(const float* __restrict__ bias, int do_relu) {
    int w = (blockIdx.x * blockDim.x + threadIdx.x) >> 5;
    int lane = threadIdx.x & 31;
    if (w >= N_NODES) return;

    const float2* gp = (const float2*)g_buf;
    float2 acc = gp[w * 32 + lane];            // self loop (already dinv-scaled)
    int s = csr_off[w], e = csr_off[w + 1];

    int k = s;
    for (; k + 4 <= e; k += 4) {
        int r0 = csr_row[k], r1 = csr_row[k + 1], r2 = csr_row[k + 2], r3 = csr_row[k + 3];
        float2 v0 = __ldg(&gp[r0 * 32 + lane]);
        float2 v1 = __ldg(&gp[r1 * 32 + lane]);
        float2 v2 = __ldg(&gp[r2 * 32 + lane]);
        float2 v3 = __ldg(&gp[r3 * 32 + lane]);
        acc.x += v0.x + v1.x + v2.x + v3.x;
        acc.y += v0.y + v1.y + v2.y + v3.y;
    }
    for (; k < e; k++) {
        float2 v = __ldg(&gp[csr_row[k] * 32 + lane]);
        acc.x += v.x;
        acc.y += v.y;
    }

    float di = dinv_buf[w];
    float o0 = di * acc.x + bias[lane * 2];
    float o1 = di * acc.y + bias[lane * 2 + 1];
    if (do_relu) { o0 = fmaxf(o0, 0.f); o1 = fmaxf(o1, 0.f); }
    ((float2*)h_buf)[w * 32 + lane] = make_float2(o0, o1);
}

// ---------------- 64x64 GEMM over node tiles (in = h_buf, out = g_buf) ----------------
__global__ void k_gemm64(const float* __restrict__ W, const float* __restrict__ bias,
                         int scale_dinv, int do_relu) {
    __shared__ float Ws[HID][HID + 1];
    __shared__ float Xs[HID][HID + 1];
    int tx = threadIdx.x;                 // 256 threads
    int base = blockIdx.x * HID;          // 64 nodes per block

    for (int l = tx; l < HID * HID; l += 256)
        Ws[l >> 6][l & 63] = W[l];
    for (int l = tx; l < HID * HID; l += 256) {
        int node = base + (l >> 6);
        Xs[l >> 6][l & 63] = (node < N_NODES) ? h_buf[node * HID + (l & 63)] : 0.f;
    }
    __syncthreads();

    int r = tx >> 2;      // node within tile
    int q = tx & 3;       // feature phase
    float acc[16];
#pragma unroll
    for (int j = 0; j < 16; j++) acc[j] = 0.f;

#pragma unroll 8
    for (int kk = 0; kk < HID; kk++) {
        float a = Xs[r][kk];
#pragma unroll
        for (int j = 0; j < 16; j++)
            acc[j] += a * Ws[kk][q + 4 * j];
    }

    int node = base + r;
    if (node < N_NODES) {
        float sc = scale_dinv ? dinv_buf[node] : 1.f;
#pragma unroll
        for (int j = 0; j < 16; j++) {
            int f = q + 4 * j;
            float v = acc[j];
            if (bias) v += bias[f];
            v *= sc;
            if (do_relu) v = fmaxf(v, 0.f);
            g_buf[node * HID + f] = v;
        }
    }
}

// ---------------- final projection: out[i] = g[i,:] . W5 + b5 ----------------
__global__ void k_final(const float* __restrict__ W5, const float* __restrict__ b5,
                        float* __restrict__ out) {
    int gw = (blockIdx.x * blockDim.x + threadIdx.x) >> 5;
    int lane = threadIdx.x & 31;
    if (gw < N_NODES) {
        const float* row = g_buf + gw * HID;
        float v = row[lane] * W5[lane] + row[lane + 32] * W5[lane + 32];
#pragma unroll
        for (int o = 16; o > 0; o >>= 1)
            v += __shfl_down_sync(0xffffffffu, v, o);
        if (lane == 0) out[gw] = v + b5[0];
    }
}

extern "C" void kernel_launch(void* const* d_in, const int* in_sizes, int n_in,
                              void* d_out, int out_size) {
    const float* x  = (const float*)d_in[0];
    const int*   ei = (const int*)d_in[1];     // edge_index int32
    const float* W1 = (const float*)d_in[3];
    const float* b1 = (const float*)d_in[4];
    const float* W2 = (const float*)d_in[5];
    const float* b2 = (const float*)d_in[6];
    const float* W3 = (const float*)d_in[7];
    const float* b3 = (const float*)d_in[8];
    const float* W4 = (const float*)d_in[9];
    const float* b4 = (const float*)d_in[10];
    const float* W5 = (const float*)d_in[11];
    const float* b5 = (const float*)d_in[12];
    float* out = (float*)d_out;

    const int nbN = (N_NODES + 255) / 256;
    const int nbE = (N_EDGES + 255) / 256;
    const int nbF = (N_NODES * HID + 255) / 256;
    const int nbG = (N_NODES + HID - 1) / HID;
    const int nbW = (N_NODES * 32 + 255) / 256;   // 1 warp per node

    // CSR build + norm
    k_zero_deg<<<nbN, 256>>>();
    k_count_deg<<<nbE, 256>>>(ei);
    k_scan1<<<NB_SCAN, SCAN_BS>>>();
    k_scan2<<<1, 256>>>();
    k_scan3<<<nbN, 256>>>();
    k_fill<<<nbE, 256>>>(ei);

    // conv1
    k_transform1<<<nbF, 256>>>(x, W1);
    k_gather<<<nbW, 256>>>(b1, 1);
    // conv2
    k_gemm64<<<nbG, 256>>>(W2, nullptr, /*scale*/1, /*relu*/0);
    k_gather<<<nbW, 256>>>(b2, 1);
    // conv3 (no relu)
    k_gemm64<<<nbG, 256>>>(W3, nullptr, /*scale*/1, /*relu*/0);
    k_gather<<<nbW, 256>>>(b3, 0);
    // dense layer 4
    k_gemm64<<<nbG, 256>>>(W4, b4, /*scale*/0, /*relu*/1);
    // output projection
    k_final<<<nbW, 256>>>(W5, b5, out);
}

// round 5
// speedup vs baseline: 2.4440x; 1.6595x over previous
#include <cuda_runtime.h>
#include <cuda_bf16.h>

#define N_NODES 100000
#define N_EDGES 1000000
#define HID 64
#define SCAN_BS 512
#define NB_SCAN ((N_NODES + SCAN_BS - 1) / SCAN_BS)   // 196

#define GT 256          // nodes per GEMM block tile
#define WS_LD 68        // padded W row
#define SMEM_GEMM ((HID * GT + HID * WS_LD) * 4)

// Scratch (device globals: allocation-free per harness rules)
__device__ __align__(16) float g_buf[N_NODES * HID];   // transform output (gather source / layer4 out)
__device__ __align__(16) float h_buf[N_NODES * HID];   // aggregated+finalized layer output
__device__ __align__(16) float px_buf[N_NODES * 2];    // dinv * x (width 2)
__device__ __align__(16) float t_buf[N_NODES * 2];     // conv1 aggregated (width 2)
__device__ float dinv_buf[N_NODES];
__device__ int   deg_buf[N_NODES];
__device__ int   incl_buf[N_NODES];
__device__ int   blksum_buf[NB_SCAN];
__device__ int   blkoff_buf[NB_SCAN];
__device__ int   csr_off[N_NODES + 1];
__device__ int   cursor_buf[N_NODES];
__device__ int   csr_row[N_EDGES];         // source nodes grouped by target

// ---------------- degree ----------------
__global__ void k_zero_deg() {
    int i = blockIdx.x * blockDim.x + threadIdx.x;
    if (i < N_NODES) deg_buf[i] = 0;
}

__global__ void k_count_deg(const int* __restrict__ ei) {
    int e = blockIdx.x * blockDim.x + threadIdx.x;
    if (e < N_EDGES) atomicAdd(&deg_buf[ei[N_EDGES + e]], 1);
}

// ---------------- 3-phase exclusive scan of deg -> csr_off ----------------
__global__ void k_scan1() {
    __shared__ int sh[SCAN_BS];
    int t = threadIdx.x;
    int i = blockIdx.x * SCAN_BS + t;
    int v = (i < N_NODES) ? deg_buf[i] : 0;
    sh[t] = v;
    __syncthreads();
    for (int off = 1; off < SCAN_BS; off <<= 1) {
        int u = (t >= off) ? sh[t - off] : 0;
        __syncthreads();
        sh[t] += u;
        __syncthreads();
    }
    if (i < N_NODES) incl_buf[i] = sh[t];
    if (t == SCAN_BS - 1) blksum_buf[blockIdx.x] = sh[t];
}

__global__ void k_scan2() {   // single block, 256 threads >= NB_SCAN; shfl scan
    __shared__ int warp_sums[8];
    int t = threadIdx.x;
    int lane = t & 31, w = t >> 5;
    int v = (t < NB_SCAN) ? blksum_buf[t] : 0;
    int s = v;
#pragma unroll
    for (int o = 1; o < 32; o <<= 1) {
        int u = __shfl_up_sync(0xffffffffu, s, o);
        if (lane >= o) s += u;
    }
    if (lane == 31) warp_sums[w] = s;
    __syncthreads();
    if (w == 0) {
        int ws = (lane < 8) ? warp_sums[lane] : 0;
#pragma unroll
        for (int o = 1; o < 8; o <<= 1) {
            int u = __shfl_up_sync(0xffffffffu, ws, o);
            if (lane >= o) ws += u;
        }
        if (lane < 8) warp_sums[lane] = ws;
    }
    __syncthreads();
    int base = (w > 0) ? warp_sums[w - 1] : 0;
    if (t < NB_SCAN) blkoff_buf[t] = base + s - v;   // exclusive
}

__global__ void k_scan3() {
    int i = blockIdx.x * blockDim.x + threadIdx.x;
    if (i < N_NODES) {
        int d = deg_buf[i];
        int excl = incl_buf[i] - d + blkoff_buf[i / SCAN_BS];
        csr_off[i] = excl;
        cursor_buf[i] = excl;
        dinv_buf[i] = rsqrtf((float)(d + 1));     // +1 self loop
        if (i == 0) csr_off[N_NODES] = N_EDGES;
    }
}

__global__ void k_fill(const int* __restrict__ ei) {
    int e = blockIdx.x * blockDim.x + threadIdx.x;
    if (e < N_EDGES) {
        int r = ei[e];
        int c = ei[N_EDGES + e];
        int pos = atomicAdd(&cursor_buf[c], 1);
        csr_row[pos] = r;
    }
}

// ---------------- conv1, width-2 path ----------------
__global__ void k_px(const float* __restrict__ x) {
    int i = blockIdx.x * blockDim.x + threadIdx.x;
    if (i < N_NODES) {
        float di = dinv_buf[i];
        float2 xv = ((const float2*)x)[i];
        ((float2*)px_buf)[i] = make_float2(di * xv.x, di * xv.y);
    }
}

__global__ void k_gather2() {     // one thread per node: t = dinv*(sum_nbr px + px_self)
    int i = blockIdx.x * blockDim.x + threadIdx.x;
    if (i < N_NODES) {
        const float2* pp = (const float2*)px_buf;
        float2 acc = pp[i];       // self loop
        int s = csr_off[i], e = csr_off[i + 1];
        int k = s;
        for (; k + 4 <= e; k += 4) {
            int r0 = csr_row[k], r1 = csr_row[k+1], r2 = csr_row[k+2], r3 = csr_row[k+3];
            float2 v0 = __ldg(&pp[r0]), v1 = __ldg(&pp[r1]);
            float2 v2 = __ldg(&pp[r2]), v3 = __ldg(&pp[r3]);
            acc.x += v0.x + v1.x + v2.x + v3.x;
            acc.y += v0.y + v1.y + v2.y + v3.y;
        }
        for (; k < e; k++) {
            float2 v = __ldg(&pp[csr_row[k]]);
            acc.x += v.x; acc.y += v.y;
        }
        float di = dinv_buf[i];
        ((float2*)t_buf)[i] = make_float2(di * acc.x, di * acc.y);
    }
}

__global__ void k_expand1(const float* __restrict__ W1, const float* __restrict__ b1) {
    // h1[i][f] = relu(t0*W1[0][f] + t1*W1[1][f] + b1[f])
    int idx = blockIdx.x * blockDim.x + threadIdx.x;  // N_NODES*16 threads, float4 each
    if (idx < N_NODES * 16) {
        int node = idx >> 4;
        int f4 = (idx & 15) * 4;
        float2 t = ((const float2*)t_buf)[node];
        float4 w0 = *(const float4*)(W1 + f4);
        float4 w1 = *(const float4*)(W1 + HID + f4);
        float4 b  = *(const float4*)(b1 + f4);
        float4 o;
        o.x = fmaxf(t.x * w0.x + t.y * w1.x + b.x, 0.f);
        o.y = fmaxf(t.x * w0.y + t.y * w1.y + b.y, 0.f);
        o.z = fmaxf(t.x * w0.z + t.y * w1.z + b.z, 0.f);
        o.w = fmaxf(t.x * w0.w + t.y * w1.w + b.w, 0.f);
        *(float4*)(h_buf + node * HID + f4) = o;
    }
}

// ---------------- fused gather-aggregate + finalize (width 64) ----------------
// h[i] = relu?( dinv[i] * (g[i] + sum_{j in N(i)} g[j]) + b )
__global__ void k_gather(const float* __restrict__ bias, int do_relu) {
    int w = (blockIdx.x * blockDim.x + threadIdx.x) >> 5;
    int lane = threadIdx.x & 31;
    if (w >= N_NODES) return;

    const float2* gp = (const float2*)g_buf;
    float2 acc = gp[w * 32 + lane];            // self loop
    int s = csr_off[w], e = csr_off[w + 1];

    int k = s;
    for (; k + 8 <= e; k += 8) {
        int r0 = csr_row[k],   r1 = csr_row[k+1], r2 = csr_row[k+2], r3 = csr_row[k+3];
        int r4 = csr_row[k+4], r5 = csr_row[k+5], r6 = csr_row[k+6], r7 = csr_row[k+7];
        float2 v0 = __ldg(&gp[r0 * 32 + lane]);
        float2 v1 = __ldg(&gp[r1 * 32 + lane]);
        float2 v2 = __ldg(&gp[r2 * 32 + lane]);
        float2 v3 = __ldg(&gp[r3 * 32 + lane]);
        float2 v4 = __ldg(&gp[r4 * 32 + lane]);
        float2 v5 = __ldg(&gp[r5 * 32 + lane]);
        float2 v6 = __ldg(&gp[r6 * 32 + lane]);
        float2 v7 = __ldg(&gp[r7 * 32 + lane]);
        acc.x += ((v0.x + v1.x) + (v2.x + v3.x)) + ((v4.x + v5.x) + (v6.x + v7.x));
        acc.y += ((v0.y + v1.y) + (v2.y + v3.y)) + ((v4.y + v5.y) + (v6.y + v7.y));
    }
    for (; k < e; k++) {
        float2 v = __ldg(&gp[csr_row[k] * 32 + lane]);
        acc.x += v.x;
        acc.y += v.y;
    }

    float di = dinv_buf[w];
    float o0 = di * acc.x + bias[lane * 2];
    float o1 = di * acc.y + bias[lane * 2 + 1];
    if (do_relu) { o0 = fmaxf(o0, 0.f); o1 = fmaxf(o1, 0.f); }
    ((float2*)h_buf)[w * 32 + lane] = make_float2(o0, o1);
}

// ---------------- register-tiled 64x64 GEMM, 256-node tiles ----------------
// g_buf[n][f] = epi( sum_k h_buf[n][k] * W[k][f] )   (buffers fixed: h_buf -> g_buf)
__global__ void k_gemm_rt(const float* __restrict__ W, const float* __restrict__ bias,
                          int scale_dinv, int do_relu) {
    extern __shared__ float sm[];
    float* Xs = sm;                 // [HID][GT] k-major
    float* Ws = sm + HID * GT;      // [HID][WS_LD]
    int tid = threadIdx.x;          // 256
    int base = blockIdx.x * GT;

    // load W (4096 floats) as float4
    for (int i = tid; i < HID * HID / 4; i += 256) {
        float4 w4 = ((const float4*)W)[i];
        int k = (i * 4) >> 6, f = (i * 4) & 63;
        *(float4*)(Ws + k * WS_LD + f) = w4;
    }
    // load X tile transposed: thread -> one node, 16 float4 reads, scatter to k-major
    {
        int node = base + tid;
        if (node < N_NODES) {
            const float4* src = (const float4*)(h_buf + node * HID);
#pragma unroll
            for (int kk = 0; kk < 16; kk++) {
                float4 v = src[kk];
                Xs[(kk * 4 + 0) * GT + tid] = v.x;
                Xs[(kk * 4 + 1) * GT + tid] = v.y;
                Xs[(kk * 4 + 2) * GT + tid] = v.z;
                Xs[(kk * 4 + 3) * GT + tid] = v.w;
            }
        } else {
#pragma unroll
            for (int kk = 0; kk < HID; kk++) Xs[kk * GT + tid] = 0.f;
        }
    }
    __syncthreads();

    int tn = tid & 7;        // feature group: f = tn*8
    int tm = tid >> 3;       // node group:    n = tm*8
    float acc[64];
#pragma unroll
    for (int i = 0; i < 64; i++) acc[i] = 0.f;

#pragma unroll 8
    for (int k = 0; k < HID; k++) {
        float4 xa = *(const float4*)(Xs + k * GT + tm * 8);
        float4 xb = *(const float4*)(Xs + k * GT + tm * 8 + 4);
        float4 wa = *(const float4*)(Ws + k * WS_LD + tn * 8);
        float4 wb = *(const float4*)(Ws + k * WS_LD + tn * 8 + 4);
        float xr[8] = {xa.x, xa.y, xa.z, xa.w, xb.x, xb.y, xb.z, xb.w};
        float wr[8] = {wa.x, wa.y, wa.z, wa.w, wb.x, wb.y, wb.z, wb.w};
#pragma unroll
        for (int i = 0; i < 8; i++)
#pragma unroll
            for (int j = 0; j < 8; j++)
                acc[i * 8 + j] += xr[i] * wr[j];
    }

    float4 ba = make_float4(0.f, 0.f, 0.f, 0.f), bb = ba;
    if (bias) {
        ba = *(const float4*)(bias + tn * 8);
        bb = *(const float4*)(bias + tn * 8 + 4);
    }
#pragma unroll
    for (int i = 0; i < 8; i++) {
        int node = base + tm * 8 + i;
        if (node < N_NODES) {
            float sc = scale_dinv ? dinv_buf[node] : 1.f;
            float4 oa, ob;
            oa.x = (acc[i*8+0] + ba.x) * sc;
            oa.y = (acc[i*8+1] + ba.y) * sc;
            oa.z = (acc[i*8+2] + ba.z) * sc;
            oa.w = (acc[i*8+3] + ba.w) * sc;
            ob.x = (acc[i*8+4] + bb.x) * sc;
            ob.y = (acc[i*8+5] + bb.y) * sc;
            ob.z = (acc[i*8+6] + bb.z) * sc;
            ob.w = (acc[i*8+7] + bb.w) * sc;
            if (do_relu) {
                oa.x = fmaxf(oa.x, 0.f); oa.y = fmaxf(oa.y, 0.f);
                oa.z = fmaxf(oa.z, 0.f); oa.w = fmaxf(oa.w, 0.f);
                ob.x = fmaxf(ob.x, 0.f); ob.y = fmaxf(ob.y, 0.f);
                ob.z = fmaxf(ob.z, 0.f); ob.w = fmaxf(ob.w, 0.f);
            }
            *(float4*)(g_buf + node * HID + tn * 8)     = oa;
            *(float4*)(g_buf + node * HID + tn * 8 + 4) = ob;
        }
    }
}

// ---------------- final projection: out[i] = g[i,:] . W5 + b5 ----------------
__global__ void k_final(const float* __restrict__ W5, const float* __restrict__ b5,
                        float* __restrict__ out) {
    int gw = (blockIdx.x * blockDim.x + threadIdx.x) >> 5;
    int lane = threadIdx.x & 31;
    if (gw < N_NODES) {
        const float* row = g_buf + gw * HID;
        float v = row[lane] * W5[lane] + row[lane + 32] * W5[lane + 32];
#pragma unroll
        for (int o = 16; o > 0; o >>= 1)
            v += __shfl_down_sync(0xffffffffu, v, o);
        if (lane == 0) out[gw] = v + b5[0];
    }
}

extern "C" void kernel_launch(void* const* d_in, const int* in_sizes, int n_in,
                              void* d_out, int out_size) {
    const float* x  = (const float*)d_in[0];
    const int*   ei = (const int*)d_in[1];     // edge_index int32
    const float* W1 = (const float*)d_in[3];
    const float* b1 = (const float*)d_in[4];
    const float* W2 = (const float*)d_in[5];
    const float* b2 = (const float*)d_in[6];
    const float* W3 = (const float*)d_in[7];
    const float* b3 = (const float*)d_in[8];
    const float* W4 = (const float*)d_in[9];
    const float* b4 = (const float*)d_in[10];
    const float* W5 = (const float*)d_in[11];
    const float* b5 = (const float*)d_in[12];
    float* out = (float*)d_out;

    static int smem_set = 0;
    if (!smem_set) {
        cudaFuncSetAttribute(k_gemm_rt, cudaFuncAttributeMaxDynamicSharedMemorySize, SMEM_GEMM);
        smem_set = 1;
    }

    const int nbN = (N_NODES + 255) / 256;
    const int nbE = (N_EDGES + 255) / 256;
    const int nbX = (N_NODES * 16 + 255) / 256;
    const int nbG = (N_NODES + GT - 1) / GT;          // 391
    const int nbW = (N_NODES * 32 + 255) / 256;       // 1 warp per node

    // CSR build + norm
    k_zero_deg<<<nbN, 256>>>();
    k_count_deg<<<nbE, 256>>>(ei);
    k_scan1<<<NB_SCAN, SCAN_BS>>>();
    k_scan2<<<1, 256>>>();
    k_scan3<<<nbN, 256>>>();
    k_fill<<<nbE, 256>>>(ei);

    // conv1 via width-2 aggregation
    k_px<<<nbN, 256>>>(x);
    k_gather2<<<nbN, 256>>>();
    k_expand1<<<nbX, 256>>>(W1, b1);

    // conv2: g = dinv*(h@W2) ; gather -> h (relu)
    k_gemm_rt<<<nbG, 256, SMEM_GEMM>>>(W2, nullptr, 1, 0);
    k_gather<<<nbW, 256>>>(b2, 1);
    // conv3
    k_gemm_rt<<<nbG, 256, SMEM_GEMM>>>(W3, nullptr, 1, 0);
    k_gather<<<nbW, 256>>>(b3, 0);
    // dense layer 4
    k_gemm_rt<<<nbG, 256, SMEM_GEMM>>>(W4, b4, 0, 1);
    // output projection
    k_final<<<nbW, 256>>>(W5, b5, out);
}